// round 9
// baseline (speedup 1.0000x reference)
#include <cuda_runtime.h>
#include <math.h>
#include <stdint.h>

#define B_    2
#define C_IN  256
#define N_TOK 2304
#define H_    8
#define DH    64
#define NKV   2305    // n + 1 null token
#define NKV_PAD 2368  // 37*64

// -------- scratch (device globals) --------
__device__ float g_invl2[B_ * N_TOK];
__device__ float g_k [B_ * H_ * NKV * DH];   // row 0 = null k, row j = q[j-1]; tf32-rounded
__device__ float g_v2[B_ * H_ * NKV * DH];   // row 0 = null v, row j = v[j-1]; tf32-rounded
__device__ float g_k2[B_ * H_ * NKV_PAD];    // per-row |k|^2 (zeros in pad)
__device__ float g_po[2 * B_ * H_ * DH * N_TOK]; // split-KV partial O (unnormalized)
__device__ float g_pl[2 * B_ * H_ * N_TOK];      // split-KV partial l
__device__ float g_o [B_ * H_ * DH * N_TOK];     // combined attn out [bh][d][i]

// -------- helpers --------
__device__ __forceinline__ uint32_t tf32b(float x) {
    uint32_t r; asm("cvt.rna.tf32.f32 %0, %1;" : "=r"(r) : "f"(x)); return r;
}
__device__ __forceinline__ void mma8(float c[4], const uint32_t a[4], uint32_t b0, uint32_t b1) {
    asm("mma.sync.aligned.m16n8k8.row.col.f32.tf32.tf32.f32 "
        "{%0,%1,%2,%3},{%4,%5,%6,%7},{%8,%9},{%0,%1,%2,%3};"
        : "+f"(c[0]), "+f"(c[1]), "+f"(c[2]), "+f"(c[3])
        : "r"(a[0]), "r"(a[1]), "r"(a[2]), "r"(a[3]), "r"(b0), "r"(b1));
}
__device__ __forceinline__ void cpasync16(uint32_t dst, const float* src) {
    asm volatile("cp.async.ca.shared.global [%0], [%1], 16;" :: "r"(dst), "l"(src));
}
__device__ __forceinline__ void cpcommit() { asm volatile("cp.async.commit_group;"); }

// ---------------- 0) null token rows ----------------
__global__ void null_init(const float* __restrict__ nullkv) {
    int tid = threadIdx.x;  // 128
#pragma unroll
    for (int t = 0; t < 8; t++) {
        int idx = tid + 128 * t;
        int bh = idx >> 6, d = idx & 63, h = bh & 7;
        g_k [(size_t)bh * NKV * DH + d] = __uint_as_float(tf32b(nullkv[h * DH + d]));
        g_v2[(size_t)bh * NKV * DH + d] = __uint_as_float(tf32b(nullkv[H_ * DH + h * DH + d]));
    }
    if (tid < 16) {
        int h = tid & 7; float s = 0.f;
#pragma unroll 8
        for (int d = 0; d < 64; d++) {
            float x = __uint_as_float(tf32b(nullkv[h * DH + d]));
            s = fmaf(x, x, s);
        }
        g_k2[(size_t)tid * NKV_PAD] = s;
    }
}

// ---------------- 1) per-token inverse L2 norm ----------------
__global__ __launch_bounds__(256) void norm_kernel(const float* __restrict__ fmap) {
    __shared__ float part[8][33];
    int i_loc = threadIdx.x & 31, cg = threadIdx.x >> 5;
    int idx = blockIdx.x * 32 + i_loc;
    int bb = idx / N_TOK, i = idx - bb * N_TOK;
    const float* p = fmap + (size_t)bb * C_IN * N_TOK + (size_t)cg * 32 * N_TOK + i;
    float s = 0.f;
#pragma unroll 8
    for (int c = 0; c < 32; c++) { float x = p[(size_t)c * N_TOK]; s = fmaf(x, x, s); }
    part[cg][i_loc] = s;
    __syncthreads();
    if (threadIdx.x < 32) {
        float t = 0.f;
#pragma unroll
        for (int g = 0; g < 8; g++) t += part[g][threadIdx.x];
        g_invl2[blockIdx.x * 32 + threadIdx.x] = 16.0f / fmaxf(sqrtf(t), 1e-12f);
    }
}

// ---------------- 2) fused qk/v projection GEMM ----------------
__global__ __launch_bounds__(256) void proj_kernel(const float* __restrict__ fmap,
                                                   const float* __restrict__ gamma,
                                                   const float* __restrict__ w_qk,
                                                   const float* __restrict__ w_v) {
    __shared__ float As[16][64];
    __shared__ float Bs[16][64];
    const int i0 = blockIdx.x * 64;
    const int o0 = blockIdx.y * 64;
    const int bb = blockIdx.z;
    const bool isv = (o0 >= 512);
    const float* W = isv ? (w_v + (o0 - 512) * C_IN) : (w_qk + o0 * C_IN);
    const int h = (isv ? (o0 - 512) : o0) >> 6;
    const int bh = bb * H_ + h;

    const int tid = threadIdx.x;
    const int tr = tid >> 4, tc = tid & 15;
    const int ii = tid & 63, kq = tid >> 6;
    const int kkb = tid & 15, ob = tid >> 4;
    const float* Ab = fmap + (size_t)bb * C_IN * N_TOK + i0;

    float acc[4][4] = {};
    for (int k0 = 0; k0 < C_IN; k0 += 16) {
#pragma unroll
        for (int t = 0; t < 4; t++) {
            int kk = kq * 4 + t;
            As[kk][ii] = Ab[(size_t)(k0 + kk) * N_TOK + ii] * gamma[k0 + kk];
        }
#pragma unroll
        for (int t = 0; t < 4; t++) {
            int o = ob + 16 * t;
            Bs[kkb][o] = W[o * C_IN + k0 + kkb];
        }
        __syncthreads();
#pragma unroll
        for (int kk = 0; kk < 16; kk++) {
            float a[4], b[4];
#pragma unroll
            for (int x = 0; x < 4; x++) a[x] = As[kk][tr * 4 + x];
#pragma unroll
            for (int y = 0; y < 4; y++) b[y] = Bs[kk][tc * 4 + y];
#pragma unroll
            for (int x = 0; x < 4; x++)
#pragma unroll
                for (int y = 0; y < 4; y++) acc[x][y] = fmaf(a[x], b[y], acc[x][y]);
        }
        __syncthreads();
    }
    float* dst = isv ? g_v2 : g_k;
#pragma unroll
    for (int x = 0; x < 4; x++) {
        int i = i0 + tr * 4 + x;
        float sc = g_invl2[bb * N_TOK + i];
        float rs = 0.f;
#pragma unroll
        for (int y = 0; y < 4; y++) {
            int d = tc * 4 + y;
            float rv = __uint_as_float(tf32b(acc[x][y] * sc));
            dst[((size_t)bh * NKV + i + 1) * DH + d] = rv;
            rs = fmaf(rv, rv, rs);
        }
        if (!isv) {
            rs += __shfl_xor_sync(0xffffffffu, rs, 1);
            rs += __shfl_xor_sync(0xffffffffu, rs, 2);
            rs += __shfl_xor_sync(0xffffffffu, rs, 4);
            rs += __shfl_xor_sync(0xffffffffu, rs, 8);
            if (tc == 0) g_k2[(size_t)bh * NKV_PAD + i + 1] = rs;
        }
    }
}

// ---------------- 3) flash attention: split-KV, m=0 softmax, P via shuffles ----------------
#define KST 68   // bank = 4*r0+cq : conflict-free
#define VST 72   // bank = 8*cq+r0 : conflict-free
#define SM_V0 (2 * 64 * KST)              // 8704 words
#define SM_K2 (SM_V0 + 2 * 64 * VST)      // 17920 words
#define SM_TOT ((SM_K2 + 128) * 4)        // 72192 B

__global__ __launch_bounds__(192, 3) void attn_mma_kernel() {
    extern __shared__ float sm[];
    const int tid = threadIdx.x, lane = tid & 31, w = tid >> 5;   // 6 warps
    const int i0 = blockIdx.x * 96;
    const int h = blockIdx.y >> 1, half = blockIdx.y & 1;
    const int bb = blockIdx.z, bh = bb * H_ + h;
    const float* kg  = g_k  + (size_t)bh * NKV * DH;
    const float* vg  = g_v2 + (size_t)bh * NKV * DH;
    const float* k2g = g_k2 + (size_t)bh * NKV_PAD;
    const float* qb  = kg + DH;          // q[i] = k[i+1]
    uint32_t smu = (uint32_t)__cvta_generic_to_shared(sm);

    const int r0 = lane >> 2, cq = lane & 3;
    const int iw  = i0 + w * 16;
    const int ig0 = iw + r0, ig1 = ig0 + 8;

    // Q fragments (tf32 bits already in gmem)
    uint32_t aq[8][4];
#pragma unroll
    for (int k = 0; k < 8; k++) {
        int c = k * 8 + cq;
        aq[k][0] = __float_as_uint(qb[(size_t)ig0 * DH + c]);
        aq[k][1] = __float_as_uint(qb[(size_t)ig1 * DH + c]);
        aq[k][2] = __float_as_uint(qb[(size_t)ig0 * DH + c + 4]);
        aq[k][3] = __float_as_uint(qb[(size_t)ig1 * DH + c + 4]);
    }
    const float q2r0 = k2g[ig0 + 1], q2r1 = k2g[ig1 + 1];

    float l0 = 0.f, l1 = 0.f;
    float o[8][4];
#pragma unroll
    for (int n = 0; n < 8; n++) { o[n][0] = o[n][1] = o[n][2] = o[n][3] = 0.f; }

    // tile loader: 1024 K chunks + 1024 V chunks + 16 k2 chunks (16B each)
    auto load_tile = [&](int buf, int j0) {
#pragma unroll
        for (int it = 0; it < 11; it++) {
            int c = tid + 192 * it;                 // 0..2111
            if (c < 2048) {
                int cc = c & 1023;
                int row = cc >> 4, seg = (cc & 15) * 4;
                int jg = j0 + row; if (jg > NKV - 1) jg = NKV - 1;
                if (c < 1024)
                    cpasync16(smu + (uint32_t)(buf * 64 * KST + row * KST + seg) * 4,
                              kg + (size_t)jg * DH + seg);
                else
                    cpasync16(smu + (uint32_t)(SM_V0 + buf * 64 * VST + row * VST + seg) * 4,
                              vg + (size_t)jg * DH + seg);
            } else if (c < 2064) {
                int cc = c - 2048;
                cpasync16(smu + (uint32_t)(SM_K2 + buf * 64 + cc * 4) * 4, k2g + j0 + cc * 4);
            }
        }
    };

    const int t_begin = half ? 19 : 0;
    const int t_end   = half ? 37 : 19;
    load_tile(0, t_begin * 64);
    cpcommit();

    for (int t = t_begin; t < t_end; t++) {
        const int j0 = t * 64, buf = (t - t_begin) & 1;
        if (t + 1 < t_end) {
            if (t > t_begin) __syncthreads();
            load_tile(buf ^ 1, (t + 1) * 64);
            cpcommit();
            asm volatile("cp.async.wait_group 1;");
        } else {
            asm volatile("cp.async.wait_group 0;");
        }
        __syncthreads();

        const uint32_t* ksb = (const uint32_t*)(sm + buf * 64 * KST);
        const uint32_t* vsb = (const uint32_t*)(sm + SM_V0 + buf * 64 * VST);
        const float*    k2s = sm + SM_K2 + buf * 64;

#pragma unroll
        for (int kb = 0; kb < 8; kb++) {
            const int jbase = j0 + kb * 8;
            if (jbase < NKV) {
                // ---- S block = Q K^T (8 mma) ----
                float sC[4] = {0.f, 0.f, 0.f, 0.f};
                {
                    int base = (kb * 8 + r0) * KST + cq;
#pragma unroll
                    for (int k = 0; k < 8; k++)
                        mma8(sC, aq[k], ksb[base + k * 8], ksb[base + k * 8 + 4]);
                }
                // ---- p = exp(-sqrt(d2)/8), m=0 ----
                float2 kk = *(const float2*)(k2s + kb * 8 + 2 * cq);
                float p0 = __expf(-0.125f * sqrtf(fmaxf(fmaf(-2.f, sC[0], q2r0 + kk.x), 0.f)));
                float p1 = __expf(-0.125f * sqrtf(fmaxf(fmaf(-2.f, sC[1], q2r0 + kk.y), 0.f)));
                float p2 = __expf(-0.125f * sqrtf(fmaxf(fmaf(-2.f, sC[2], q2r1 + kk.x), 0.f)));
                float p3 = __expf(-0.125f * sqrtf(fmaxf(fmaf(-2.f, sC[3], q2r1 + kk.y), 0.f)));
                // masks: warp-uniform guard; inner compares only near the diagonal / tail
                if ((jbase <= iw + 16 && jbase + 8 > iw + 1) || (jbase + 8 > NKV)) {
                    int jb = jbase + 2 * cq;
                    if (jb == ig0 + 1 || jb >= NKV)     p0 = 0.f;
                    if (jb + 1 == ig0 + 1 || jb + 1 >= NKV) p1 = 0.f;
                    if (jb == ig1 + 1 || jb >= NKV)     p2 = 0.f;
                    if (jb + 1 == ig1 + 1 || jb + 1 >= NKV) p3 = 0.f;
                }
                l0 += p0 + p1; l1 += p2 + p3;
                // ---- C-fragment -> A-fragment via shuffles ----
                uint32_t pu0 = tf32b(p0), pu1 = tf32b(p1), pu2 = tf32b(p2), pu3 = tf32b(p3);
                int src0 = r0 * 4 + (cq >> 1), src1 = src0 + 2;
                uint32_t t0 = __shfl_sync(~0u, pu0, src0), t1 = __shfl_sync(~0u, pu1, src0);
                uint32_t t2 = __shfl_sync(~0u, pu2, src0), t3 = __shfl_sync(~0u, pu3, src0);
                uint32_t u0 = __shfl_sync(~0u, pu0, src1), u1 = __shfl_sync(~0u, pu1, src1);
                uint32_t u2 = __shfl_sync(~0u, pu2, src1), u3 = __shfl_sync(~0u, pu3, src1);
                uint32_t ap[4];
                bool odd = (cq & 1);
                ap[0] = odd ? t1 : t0;
                ap[1] = odd ? t3 : t2;
                ap[2] = odd ? u1 : u0;
                ap[3] = odd ? u3 : u2;
                // ---- O += P(kb) V(kb) (8 mma) ----
                {
                    int vbase = (kb * 8 + cq) * VST + r0;
#pragma unroll
                    for (int n = 0; n < 8; n++)
                        mma8(o[n], ap, vsb[vbase + n * 8], vsb[vbase + 4 * VST + n * 8]);
                }
            }
        }
    }

    // ---- epilogue: write unnormalized partials ----
    l0 += __shfl_xor_sync(~0u, l0, 1); l0 += __shfl_xor_sync(~0u, l0, 2);
    l1 += __shfl_xor_sync(~0u, l1, 1); l1 += __shfl_xor_sync(~0u, l1, 2);
    float* ob = g_po + (size_t)(half * 16 + bh) * DH * N_TOK;
#pragma unroll
    for (int n = 0; n < 8; n++) {
        int d = n * 8 + 2 * cq;
        ob[(size_t)d * N_TOK + ig0]       = o[n][0];
        ob[(size_t)(d + 1) * N_TOK + ig0] = o[n][1];
        ob[(size_t)d * N_TOK + ig1]       = o[n][2];
        ob[(size_t)(d + 1) * N_TOK + ig1] = o[n][3];
    }
    if (cq == 0) {
        g_pl[(size_t)(half * 16 + bh) * N_TOK + ig0] = l0;
        g_pl[(size_t)(half * 16 + bh) * N_TOK + ig1] = l1;
    }
}

// ---------------- 3b) combine split-KV halves ----------------
__global__ __launch_bounds__(256) void combine_kernel() {
    const int c = blockIdx.x * 256 + threadIdx.x;      // float4 index
    const int base = c * 4;
    const int i  = base % N_TOK;
    const int bh = (base / N_TOK) >> 6;
    const float4 a = *(const float4*)(g_po + base);
    const float4 b = *(const float4*)(g_po + (size_t)16 * DH * N_TOK + base);
    const float4 la = *(const float4*)(g_pl + (size_t)bh * N_TOK + i);
    const float4 lb = *(const float4*)(g_pl + (size_t)(16 + bh) * N_TOK + i);
    float4 r;
    r.x = __fdividef(a.x + b.x, la.x + lb.x);
    r.y = __fdividef(a.y + b.y, la.y + lb.y);
    r.z = __fdividef(a.z + b.z, la.z + lb.z);
    r.w = __fdividef(a.w + b.w, la.w + lb.w);
    *(float4*)(g_o + base) = r;
}

// ---------------- 4) output projection GEMM ----------------
__global__ __launch_bounds__(128) void outproj_kernel(const float* __restrict__ w_out,
                                                      float* __restrict__ out) {
    __shared__ float As[16][32];
    __shared__ float Bs[16][64];
    const int n0 = blockIdx.x * 64, o0 = blockIdx.y * 32, bb = blockIdx.z;
    const int tid = threadIdx.x, tr = tid >> 4, tc = tid & 15;
    const int kkA = tid & 15, oA = tid >> 4;
    const int nB = tid & 63, kB = tid >> 6;
    float acc[4][4] = {};
    for (int k0 = 0; k0 < 512; k0 += 16) {
#pragma unroll
        for (int t = 0; t < 4; t++) {
            int o = oA + 8 * t;
            As[kkA][o] = w_out[(o0 + o) * 512 + k0 + kkA];
        }
#pragma unroll
        for (int t = 0; t < 8; t++) {
            int kk = kB + 2 * t;
            Bs[kk][nB] = g_o[((size_t)bb * 512 + k0 + kk) * N_TOK + n0 + nB];
        }
        __syncthreads();
#pragma unroll
        for (int kk = 0; kk < 16; kk++) {
            float a[4], b[4];
#pragma unroll
            for (int x = 0; x < 4; x++) a[x] = As[kk][tr * 4 + x];
#pragma unroll
            for (int y = 0; y < 4; y++) b[y] = Bs[kk][tc * 4 + y];
#pragma unroll
            for (int x = 0; x < 4; x++)
#pragma unroll
                for (int y = 0; y < 4; y++) acc[x][y] = fmaf(a[x], b[y], acc[x][y]);
        }
        __syncthreads();
    }
#pragma unroll
    for (int x = 0; x < 4; x++)
#pragma unroll
        for (int y = 0; y < 4; y++)
            out[(size_t)bb * 256 * N_TOK + (size_t)(o0 + tr * 4 + x) * N_TOK + n0 + tc * 4 + y] = acc[x][y];
}

// ---------------- launch ----------------
extern "C" void kernel_launch(void* const* d_in, const int* in_sizes, int n_in,
                              void* d_out, int out_size) {
    const float* fmap   = (const float*)d_in[0];
    const float* gamma  = (const float*)d_in[1];
    const float* w_qk   = (const float*)d_in[2];
    const float* w_v    = (const float*)d_in[3];
    const float* nullkv = (const float*)d_in[4];
    const float* w_out  = (const float*)d_in[5];
    float* out = (float*)d_out;

    cudaFuncSetAttribute(attn_mma_kernel, cudaFuncAttributeMaxDynamicSharedMemorySize, SM_TOT);

    null_init<<<1, 128>>>(nullkv);
    norm_kernel<<<(B_ * N_TOK) / 32, 256>>>(fmap);
    proj_kernel<<<dim3(N_TOK / 64, 16, B_), 256>>>(fmap, gamma, w_qk, w_v);
    attn_mma_kernel<<<dim3(N_TOK / 96, H_ * 2, B_), 192, SM_TOT>>>();
    combine_kernel<<<(B_ * H_ * DH * N_TOK / 4) / 256, 256>>>();
    outproj_kernel<<<dim3(N_TOK / 64, 8, B_), 128>>>(w_out, out);
}

// round 10
// speedup vs baseline: 1.1759x; 1.1759x over previous
#include <cuda_runtime.h>
#include <cuda_fp16.h>
#include <math.h>
#include <stdint.h>

#define B_    2
#define C_IN  256
#define N_TOK 2304
#define H_    8
#define DH    64
#define NKV   2305    // n + 1 null token
#define NKVP  2368    // padded (37*64)

typedef unsigned int u32;

// -------- scratch (device globals, zero-init) --------
__device__ float  g_invl2[B_ * N_TOK];
__device__ __half g_kb[B_ * H_ * NKV * DH];    // [bh][j][d]; row0=null k, row j=q[j-1]; f16
__device__ __half g_vT[B_ * H_ * DH * NKVP];   // [bh][d][j]; col0=null v; f16; pad zeros
__device__ float  g_k2[B_ * H_ * NKVP];        // |k|^2 of f16-rounded rows; pad zeros
__device__ float  g_o [B_ * H_ * DH * N_TOK];  // attn out [bh][d][i] fp32

// -------- helpers --------
__device__ __forceinline__ void mmaf16(float c[4], const u32 a[4], u32 b0, u32 b1) {
    asm("mma.sync.aligned.m16n8k16.row.col.f32.f16.f16.f32 "
        "{%0,%1,%2,%3},{%4,%5,%6,%7},{%8,%9},{%0,%1,%2,%3};"
        : "+f"(c[0]), "+f"(c[1]), "+f"(c[2]), "+f"(c[3])
        : "r"(a[0]), "r"(a[1]), "r"(a[2]), "r"(a[3]), "r"(b0), "r"(b1));
}
__device__ __forceinline__ u32 packh2(float hi, float lo) {
    u32 r; asm("cvt.rn.f16x2.f32 %0, %1, %2;" : "=r"(r) : "f"(hi), "f"(lo)); return r;
}
__device__ __forceinline__ void cpasync16(u32 dst, const void* src) {
    asm volatile("cp.async.ca.shared.global [%0], [%1], 16;" :: "r"(dst), "l"(src));
}
__device__ __forceinline__ void cpcommit() { asm volatile("cp.async.commit_group;"); }

// ---------------- 0) null token rows ----------------
__global__ void null_init(const float* __restrict__ nullkv) {
    int tid = threadIdx.x;  // 128
#pragma unroll
    for (int t = 0; t < 8; t++) {
        int idx = tid + 128 * t;                 // 0..1023
        int bh = idx >> 6, d = idx & 63, h = bh & 7;
        g_kb[(size_t)bh * NKV * DH + d]  = __float2half_rn(nullkv[h * DH + d]);
        g_vT[((size_t)bh * DH + d) * NKVP] = __float2half_rn(nullkv[H_ * DH + h * DH + d]);
    }
    if (tid < 16) {
        int h = tid & 7; float s = 0.f;
#pragma unroll 8
        for (int d = 0; d < 64; d++) {
            float x = __half2float(__float2half_rn(nullkv[h * DH + d]));
            s = fmaf(x, x, s);
        }
        g_k2[(size_t)tid * NKVP] = s;
    }
}

// ---------------- 1) per-token inverse L2 norm ----------------
__global__ __launch_bounds__(256) void norm_kernel(const float* __restrict__ fmap) {
    __shared__ float part[8][33];
    int i_loc = threadIdx.x & 31, cg = threadIdx.x >> 5;
    int idx = blockIdx.x * 32 + i_loc;
    int bb = idx / N_TOK, i = idx - bb * N_TOK;
    const float* p = fmap + (size_t)bb * C_IN * N_TOK + (size_t)cg * 32 * N_TOK + i;
    float s = 0.f;
#pragma unroll 8
    for (int c = 0; c < 32; c++) { float x = p[(size_t)c * N_TOK]; s = fmaf(x, x, s); }
    part[cg][i_loc] = s;
    __syncthreads();
    if (threadIdx.x < 32) {
        float t = 0.f;
#pragma unroll
        for (int g = 0; g < 8; g++) t += part[g][threadIdx.x];
        g_invl2[blockIdx.x * 32 + threadIdx.x] = 16.0f / fmaxf(sqrtf(t), 1e-12f);
    }
}

// ---------------- 2) fused qk/v projection GEMM ----------------
__global__ __launch_bounds__(256) void proj_kernel(const float* __restrict__ fmap,
                                                   const float* __restrict__ gamma,
                                                   const float* __restrict__ w_qk,
                                                   const float* __restrict__ w_v) {
    __shared__ float As[16][64];
    __shared__ float Bs[16][64];
    const int i0 = blockIdx.x * 64;
    const int o0 = blockIdx.y * 64;
    const int bb = blockIdx.z;
    const bool isv = (o0 >= 512);
    const float* W = isv ? (w_v + (o0 - 512) * C_IN) : (w_qk + o0 * C_IN);
    const int h = (isv ? (o0 - 512) : o0) >> 6;
    const int bh = bb * H_ + h;

    const int tid = threadIdx.x;
    const int tr = tid >> 4, tc = tid & 15;
    const int ii = tid & 63, kq = tid >> 6;
    const int kkb = tid & 15, ob = tid >> 4;
    const float* Ab = fmap + (size_t)bb * C_IN * N_TOK + i0;

    float acc[4][4] = {};
    for (int k0 = 0; k0 < C_IN; k0 += 16) {
#pragma unroll
        for (int t = 0; t < 4; t++) {
            int kk = kq * 4 + t;
            As[kk][ii] = Ab[(size_t)(k0 + kk) * N_TOK + ii] * gamma[k0 + kk];
        }
#pragma unroll
        for (int t = 0; t < 4; t++) {
            int o = ob + 16 * t;
            Bs[kkb][o] = W[o * C_IN + k0 + kkb];
        }
        __syncthreads();
#pragma unroll
        for (int kk = 0; kk < 16; kk++) {
            float a[4], b[4];
#pragma unroll
            for (int x = 0; x < 4; x++) a[x] = As[kk][tr * 4 + x];
#pragma unroll
            for (int y = 0; y < 4; y++) b[y] = Bs[kk][tc * 4 + y];
#pragma unroll
            for (int x = 0; x < 4; x++)
#pragma unroll
                for (int y = 0; y < 4; y++) acc[x][y] = fmaf(a[x], b[y], acc[x][y]);
        }
        __syncthreads();
    }
#pragma unroll
    for (int x = 0; x < 4; x++) {
        int i = i0 + tr * 4 + x;
        float sc = g_invl2[bb * N_TOK + i];
        if (!isv) {
            float rs = 0.f;
#pragma unroll
            for (int y = 0; y < 4; y++) {
                int d = tc * 4 + y;
                __half hv = __float2half_rn(acc[x][y] * sc);
                g_kb[((size_t)bh * NKV + i + 1) * DH + d] = hv;
                float rv = __half2float(hv);
                rs = fmaf(rv, rv, rs);
            }
            rs += __shfl_xor_sync(0xffffffffu, rs, 1);
            rs += __shfl_xor_sync(0xffffffffu, rs, 2);
            rs += __shfl_xor_sync(0xffffffffu, rs, 4);
            rs += __shfl_xor_sync(0xffffffffu, rs, 8);
            if (tc == 0) g_k2[(size_t)bh * NKVP + i + 1] = rs;
        } else {
#pragma unroll
            for (int y = 0; y < 4; y++) {
                int d = tc * 4 + y;
                g_vT[((size_t)bh * DH + d) * NKVP + i + 1] = __float2half_rn(acc[x][y] * sc);
            }
        }
    }
}

// ---------------- 3) flash attention: f16 m16n8k16, m=0 softmax, swizzled smem ----------------
// smem word layout (4B words):
#define SMK_W  0                  // K tiles: 2 x 64 rows x 32 words (f16x2), XOR-swizzled
#define SMV_W  4096               // V^T tiles: same shape
#define SMK2_W 8192               // k2: 2 x 64 floats
#define SMP_W  8320               // P: 8 warps x 16 rows x 36 words
#define SM_TOT ((SMP_W + 8 * 16 * 36) * 4)   // 51712 B

__global__ __launch_bounds__(256, 3) void attn_mma_kernel() {
    extern __shared__ float sm[];
    u32* smw = (u32*)sm;
    const int tid = threadIdx.x, lane = tid & 31, w = tid >> 5;   // 8 warps
    const int i0 = blockIdx.x * 128, h = blockIdx.y, bb = blockIdx.z;
    const int bh = bb * H_ + h;
    const __half* kb_g = g_kb + (size_t)bh * NKV * DH;
    const __half* vT_g = g_vT + (size_t)bh * DH * NKVP;
    const float*  k2g  = g_k2 + (size_t)bh * NKVP;
    u32 smu = (u32)__cvta_generic_to_shared(sm);

    const int r0 = lane >> 2, cq = lane & 3;
    const int iw  = i0 + w * 16;
    const int ig0 = iw + r0, ig1 = ig0 + 8;

    // Q A-fragments: q[i] = k[i+1]; f16 pairs direct from gmem
    u32 aq[4][4];
    {
        const __half* q0 = kb_g + (size_t)(ig0 + 1) * DH;
        const __half* q1 = kb_g + (size_t)(ig1 + 1) * DH;
#pragma unroll
        for (int kk = 0; kk < 4; kk++) {
            int d = kk * 16 + 2 * cq;
            aq[kk][0] = *(const u32*)(q0 + d);
            aq[kk][1] = *(const u32*)(q1 + d);
            aq[kk][2] = *(const u32*)(q0 + d + 8);
            aq[kk][3] = *(const u32*)(q1 + d + 8);
        }
    }
    const float q2r0 = k2g[ig0 + 1], q2r1 = k2g[ig1 + 1];

    float l0 = 0.f, l1 = 0.f;
    float o[8][4];
#pragma unroll
    for (int n = 0; n < 8; n++) { o[n][0] = o[n][1] = o[n][2] = o[n][3] = 0.f; }

    // tile loader: K 512 chunks + V 512 + k2 16 (16B each)
    auto load_tile = [&](int buf, int j0) {
#pragma unroll
        for (int it = 0; it < 5; it++) {
            int c = tid + 256 * it;                    // 0..1279, used < 1040
            if (c < 512) {
                int row = c >> 3, ch = c & 7, sw = ch ^ (row & 7);
                int jg = j0 + row; if (jg > NKV - 1) jg = NKV - 1;
                cpasync16(smu + (u32)(SMK_W + buf * 2048 + row * 32 + sw * 4) * 4,
                          kb_g + (size_t)jg * DH + ch * 8);
            } else if (c < 1024) {
                int cc = c - 512;
                int row = cc >> 3, ch = cc & 7, sw = ch ^ (row & 7);
                cpasync16(smu + (u32)(SMV_W + buf * 2048 + row * 32 + sw * 4) * 4,
                          vT_g + (size_t)row * NKVP + j0 + ch * 8);
            } else if (c < 1040) {
                int cc = c - 1024;
                cpasync16(smu + (u32)(SMK2_W + buf * 64 + cc * 4) * 4, k2g + j0 + cc * 4);
            }
        }
    };

    load_tile(0, 0);
    cpcommit();

    const int NT = (NKV + 63) / 64;   // 37
    for (int t = 0; t < NT; t++) {
        const int j0 = t * 64, buf = t & 1;
        if (t + 1 < NT) {
            if (t >= 1) __syncthreads();
            load_tile(buf ^ 1, j0 + 64);
            cpcommit();
            asm volatile("cp.async.wait_group 1;");
        } else {
            asm volatile("cp.async.wait_group 0;");
        }
        __syncthreads();

        const u32* ksb = smw + SMK_W + buf * 2048;
        const u32* vsb = smw + SMV_W + buf * 2048;
        const float* k2s = sm + SMK2_W + buf * 64;
        u32* pw = smw + SMP_W + w * 16 * 36;

        // ---- S = Q K^T (32 mma) ----
        float sC[8][4];
#pragma unroll
        for (int n = 0; n < 8; n++) {
            sC[n][0] = sC[n][1] = sC[n][2] = sC[n][3] = 0.f;
            int rb = (n * 8 + r0) * 32;
#pragma unroll
            for (int kk = 0; kk < 4; kk++) {
                u32 b0 = ksb[rb + (((2 * kk)     ^ r0) * 4) + cq];
                u32 b1 = ksb[rb + (((2 * kk + 1) ^ r0) * 4) + cq];
                mmaf16(sC[n], aq[kk], b0, b1);
            }
        }

        // ---- p = exp(-sqrt(d2)/8) (m=0), masks, l accumulate ----
#pragma unroll
        for (int n = 0; n < 8; n++) {
            int jbase = j0 + n * 8;
            float2 kk2 = *(const float2*)(k2s + n * 8 + 2 * cq);
            float p0 = __expf(-0.125f * sqrtf(fmaxf(fmaf(-2.f, sC[n][0], q2r0 + kk2.x), 0.f)));
            float p1 = __expf(-0.125f * sqrtf(fmaxf(fmaf(-2.f, sC[n][1], q2r0 + kk2.y), 0.f)));
            float p2 = __expf(-0.125f * sqrtf(fmaxf(fmaf(-2.f, sC[n][2], q2r1 + kk2.x), 0.f)));
            float p3 = __expf(-0.125f * sqrtf(fmaxf(fmaf(-2.f, sC[n][3], q2r1 + kk2.y), 0.f)));
            if ((jbase <= iw + 16 && jbase + 8 > iw + 1) || (jbase + 8 > NKV)) {
                int jb = jbase + 2 * cq;
                if (jb == ig0 + 1 || jb >= NKV)         p0 = 0.f;
                if (jb + 1 == ig0 + 1 || jb + 1 >= NKV) p1 = 0.f;
                if (jb == ig1 + 1 || jb >= NKV)         p2 = 0.f;
                if (jb + 1 == ig1 + 1 || jb + 1 >= NKV) p3 = 0.f;
            }
            l0 += p0 + p1; l1 += p2 + p3;
            sC[n][0] = p0; sC[n][1] = p1; sC[n][2] = p2; sC[n][3] = p3;
        }

        // ---- stage P as f16x2 (per-warp region) ----
#pragma unroll
        for (int n = 0; n < 8; n++) {
            pw[r0 * 36 + n * 4 + cq]       = packh2(sC[n][1], sC[n][0]);
            pw[(r0 + 8) * 36 + n * 4 + cq] = packh2(sC[n][3], sC[n][2]);
        }
        __syncwarp();

        // ---- O += P V (32 mma) ----
#pragma unroll
        for (int kk = 0; kk < 4; kk++) {
            u32 ap[4];
            ap[0] = pw[r0 * 36 + kk * 8 + cq];
            ap[1] = pw[(r0 + 8) * 36 + kk * 8 + cq];
            ap[2] = pw[r0 * 36 + kk * 8 + cq + 4];
            ap[3] = pw[(r0 + 8) * 36 + kk * 8 + cq + 4];
#pragma unroll
            for (int n = 0; n < 8; n++) {
                int rb = (n * 8 + r0) * 32;
                u32 b0 = vsb[rb + (((2 * kk)     ^ r0) * 4) + cq];
                u32 b1 = vsb[rb + (((2 * kk + 1) ^ r0) * 4) + cq];
                mmaf16(o[n], ap, b0, b1);
            }
        }
    }

    // ---- epilogue: /l, write g_o [bh][d][i] ----
    l0 += __shfl_xor_sync(~0u, l0, 1); l0 += __shfl_xor_sync(~0u, l0, 2);
    l1 += __shfl_xor_sync(~0u, l1, 1); l1 += __shfl_xor_sync(~0u, l1, 2);
    float inv0 = 1.f / l0, inv1 = 1.f / l1;
    float* ob = g_o + (size_t)bh * DH * N_TOK;
#pragma unroll
    for (int n = 0; n < 8; n++) {
        int d = n * 8 + 2 * cq;
        ob[(size_t)d * N_TOK + ig0]       = o[n][0] * inv0;
        ob[(size_t)(d + 1) * N_TOK + ig0] = o[n][1] * inv0;
        ob[(size_t)d * N_TOK + ig1]       = o[n][2] * inv1;
        ob[(size_t)(d + 1) * N_TOK + ig1] = o[n][3] * inv1;
    }
}

// ---------------- 4) output projection GEMM ----------------
__global__ __launch_bounds__(128) void outproj_kernel(const float* __restrict__ w_out,
                                                      float* __restrict__ out) {
    __shared__ float As[16][32];
    __shared__ float Bs[16][64];
    const int n0 = blockIdx.x * 64, o0 = blockIdx.y * 32, bb = blockIdx.z;
    const int tid = threadIdx.x, tr = tid >> 4, tc = tid & 15;
    const int kkA = tid & 15, oA = tid >> 4;
    const int nB = tid & 63, kB = tid >> 6;
    float acc[4][4] = {};
    for (int k0 = 0; k0 < 512; k0 += 16) {
#pragma unroll
        for (int t = 0; t < 4; t++) {
            int o = oA + 8 * t;
            As[kkA][o] = w_out[(o0 + o) * 512 + k0 + kkA];
        }
#pragma unroll
        for (int t = 0; t < 8; t++) {
            int kk = kB + 2 * t;
            Bs[kk][nB] = g_o[((size_t)bb * 512 + k0 + kk) * N_TOK + n0 + nB];
        }
        __syncthreads();
#pragma unroll
        for (int kk = 0; kk < 16; kk++) {
            float a[4], b[4];
#pragma unroll
            for (int x = 0; x < 4; x++) a[x] = As[kk][tr * 4 + x];
#pragma unroll
            for (int y = 0; y < 4; y++) b[y] = Bs[kk][tc * 4 + y];
#pragma unroll
            for (int x = 0; x < 4; x++)
#pragma unroll
                for (int y = 0; y < 4; y++) acc[x][y] = fmaf(a[x], b[y], acc[x][y]);
        }
        __syncthreads();
    }
#pragma unroll
    for (int x = 0; x < 4; x++)
#pragma unroll
        for (int y = 0; y < 4; y++)
            out[(size_t)bb * 256 * N_TOK + (size_t)(o0 + tr * 4 + x) * N_TOK + n0 + tc * 4 + y] = acc[x][y];
}

// ---------------- launch ----------------
extern "C" void kernel_launch(void* const* d_in, const int* in_sizes, int n_in,
                              void* d_out, int out_size) {
    const float* fmap   = (const float*)d_in[0];
    const float* gamma  = (const float*)d_in[1];
    const float* w_qk   = (const float*)d_in[2];
    const float* w_v    = (const float*)d_in[3];
    const float* nullkv = (const float*)d_in[4];
    const float* w_out  = (const float*)d_in[5];
    float* out = (float*)d_out;

    cudaFuncSetAttribute(attn_mma_kernel, cudaFuncAttributeMaxDynamicSharedMemorySize, SM_TOT);

    null_init<<<1, 128>>>(nullkv);
    norm_kernel<<<(B_ * N_TOK) / 32, 256>>>(fmap);
    proj_kernel<<<dim3(N_TOK / 64, 16, B_), 256>>>(fmap, gamma, w_qk, w_v);
    attn_mma_kernel<<<dim3(N_TOK / 128, H_, B_), 256, SM_TOT>>>();
    outproj_kernel<<<dim3(N_TOK / 64, 8, B_), 128>>>(w_out, out);
}